// round 8
// baseline (speedup 1.0000x reference)
#include <cuda_runtime.h>
#include <cuda_bf16.h>
#include <cstdint>

#define BDIM 2
#define TSEQ 2048
#define NH 16
#define HD 64
#define DM 1024
#define MTOT (BDIM*TSEQ)

// ---------------- scratch (allocation-free: __device__ globals) ----------------
__device__ uint4 g_xhi[(size_t)MTOT*DM*2/16],  g_xlo[(size_t)MTOT*DM*2/16];
__device__ uint4 g_w1hi[(size_t)3*DM*DM*2/16], g_w1lo[(size_t)3*DM*DM*2/16];
__device__ uint4 g_w2hi[(size_t)DM*DM*2/16],   g_w2lo[(size_t)DM*DM*2/16];
__device__ uint4 g_qhi[(size_t)BDIM*NH*TSEQ*HD*2/16];
__device__ uint4 g_khi[(size_t)BDIM*NH*TSEQ*HD*2/16], g_klo[(size_t)BDIM*NH*TSEQ*HD*2/16];
__device__ uint4 g_vhi[(size_t)BDIM*NH*TSEQ*HD*2/16], g_vlo[(size_t)BDIM*NH*TSEQ*HD*2/16];
__device__ uint4 g_ahi[(size_t)MTOT*DM*2/16],  g_alo[(size_t)MTOT*DM*2/16];

// ---------------- helpers ----------------
__device__ __forceinline__ uint32_t smem_u32(const void* p) {
    uint32_t a;
    asm("{ .reg .u64 t; cvta.to.shared.u64 t, %1; cvt.u32.u64 %0, t; }" : "=r"(a) : "l"(p));
    return a;
}
__device__ __forceinline__ void cpasync16(uint32_t dst, const void* src) {
    asm volatile("cp.async.cg.shared.global [%0], [%1], 16;" :: "r"(dst), "l"(src) : "memory");
}
#define CP_COMMIT() asm volatile("cp.async.commit_group;" ::: "memory")
#define CP_WAIT1()  asm volatile("cp.async.wait_group 1;" ::: "memory")
#define CP_WAIT0()  asm volatile("cp.async.wait_group 0;" ::: "memory")
__device__ __forceinline__ void ldsm4(uint32_t* r, uint32_t addr) {
    asm volatile("ldmatrix.sync.aligned.m8n8.x4.shared.b16 {%0,%1,%2,%3}, [%4];"
        : "=r"(r[0]), "=r"(r[1]), "=r"(r[2]), "=r"(r[3]) : "r"(addr));
}
__device__ __forceinline__ void ldsm4t(uint32_t* r, uint32_t addr) {
    asm volatile("ldmatrix.sync.aligned.m8n8.x4.trans.shared.b16 {%0,%1,%2,%3}, [%4];"
        : "=r"(r[0]), "=r"(r[1]), "=r"(r[2]), "=r"(r[3]) : "r"(addr));
}
__device__ __forceinline__ void mma_bf16(float* c, const uint32_t* a, const uint32_t* b) {
    asm volatile(
        "mma.sync.aligned.m16n8k16.row.col.f32.bf16.bf16.f32 "
        "{%0,%1,%2,%3}, {%4,%5,%6,%7}, {%8,%9}, {%0,%1,%2,%3};"
        : "+f"(c[0]), "+f"(c[1]), "+f"(c[2]), "+f"(c[3])
        : "r"(a[0]), "r"(a[1]), "r"(a[2]), "r"(a[3]), "r"(b[0]), "r"(b[1]));
}
__device__ __forceinline__ unsigned short bfbits(__nv_bfloat16 h) {
    return reinterpret_cast<unsigned short&>(h);
}
__device__ __forceinline__ uint32_t pack_hilo(float a, float b, float* ra, float* rb) {
    __nv_bfloat16 ha = __float2bfloat16(a), hb = __float2bfloat16(b);
    *ra = a - __bfloat162float(ha);
    *rb = b - __bfloat162float(hb);
    return (uint32_t)bfbits(ha) | ((uint32_t)bfbits(hb) << 16);
}
__device__ __forceinline__ uint32_t pack_bf(float a, float b) {
    return (uint32_t)bfbits(__float2bfloat16(a)) | ((uint32_t)bfbits(__float2bfloat16(b)) << 16);
}

// ---------------- fused fp32 -> bf16 hi/lo split over 3 tensors ----------------
#define SPLIT_N0 (MTOT*DM/4)
#define SPLIT_N1 (3*DM*DM/4)
#define SPLIT_N2 (DM*DM/4)
#define SPLIT_TOT (SPLIT_N0 + SPLIT_N1 + SPLIT_N2)

__global__ __launch_bounds__(256)
void split3_kernel(const float* __restrict__ s0, const float* __restrict__ s1,
                   const float* __restrict__ s2)
{
    int i = blockIdx.x * blockDim.x + threadIdx.x;
    if (i >= SPLIT_TOT) return;
    const float* s; __nv_bfloat16 *hi, *lo; int j;
    if (i < SPLIT_N0) {
        s = s0; hi = (__nv_bfloat16*)g_xhi; lo = (__nv_bfloat16*)g_xlo; j = i;
    } else if (i < SPLIT_N0 + SPLIT_N1) {
        s = s1; hi = (__nv_bfloat16*)g_w1hi; lo = (__nv_bfloat16*)g_w1lo; j = i - SPLIT_N0;
    } else {
        s = s2; hi = (__nv_bfloat16*)g_w2hi; lo = (__nv_bfloat16*)g_w2lo; j = i - SPLIT_N0 - SPLIT_N1;
    }
    float4 v = ((const float4*)s)[j];
    float f[4] = {v.x, v.y, v.z, v.w};
    unsigned short h[4], l[4];
    #pragma unroll
    for (int k = 0; k < 4; k++) {
        __nv_bfloat16 hb = __float2bfloat16(f[k]);
        __nv_bfloat16 lb = __float2bfloat16(f[k] - __bfloat162float(hb));
        h[k] = bfbits(hb); l[k] = bfbits(lb);
    }
    ((ushort4*)hi)[j] = make_ushort4(h[0], h[1], h[2], h[3]);
    ((ushort4*)lo)[j] = make_ushort4(l[0], l[1], l[2], l[3]);
}

// ---------------- persistent mma.sync GEMM, 3-stage pipeline ----------------
#define BK 32
#define NCH (DM / BK)
#define TILE_B 8192
#define STAGE_B (4 * TILE_B)
#define GSTAGES 3
#define GEMM_SMEM (GSTAGES * STAGE_B)   // 98304

template<bool SCATTER>
__global__ __launch_bounds__(256, 2)
void mma_gemm(const __nv_bfloat16* __restrict__ Ahi, const __nv_bfloat16* __restrict__ Alo,
              const __nv_bfloat16* __restrict__ Whi, const __nv_bfloat16* __restrict__ Wlo,
              const float* __restrict__ bias, float* __restrict__ C, int N)
{
    extern __shared__ char smem[];
    const uint32_t sbase = smem_u32(smem);
    const int tid = threadIdx.x, wid = tid >> 5, lane = tid & 31;
    const int wm = wid & 3, wn = wid >> 2;
    const int K = DM;
    const int nx = N >> 7;
    const int ntile = (MTOT >> 7) * nx;
    const int ntile_own = (ntile - (int)blockIdx.x + (int)gridDim.x - 1) / (int)gridDim.x;
    const int F = ntile_own << 5;

    auto load_flat = [&](int ff) {
        const int tl = ff >> 5;
        const int tile = (int)blockIdx.x + tl * (int)gridDim.x;
        const int c = ff & 31;
        const int m0 = (tile / nx) << 7, n0 = (tile % nx) << 7;
        const uint32_t st = sbase + (uint32_t)(ff % 3) * STAGE_B;
        const int k0 = c * BK;
        #pragma unroll
        for (int t = 0; t < 2; t++) {
            int idx = tid + t * 256;
            int row = idx >> 2, ch = idx & 3;
            uint32_t so = (uint32_t)(row * 64 + ((ch ^ ((row >> 1) & 3)) * 16));
            int gk = k0 + ch * 8;
            const size_t ea = (size_t)(m0 + row) * K + gk;
            const size_t ew = (size_t)(n0 + row) * K + gk;
            cpasync16(st + so,              Ahi + ea);
            cpasync16(st + TILE_B + so,     Alo + ea);
            cpasync16(st + 2*TILE_B + so,   Whi + ew);
            cpasync16(st + 3*TILE_B + so,   Wlo + ew);
        }
        CP_COMMIT();
    };

    const int arowoff = lane & 15;
    const int akoff   = lane >> 4;
    const int browoff = (lane & 7) + ((lane >> 4) << 3);
    const int bkoff   = (lane >> 3) & 1;

    int rowA[2], swA[2];
    #pragma unroll
    for (int mt = 0; mt < 2; mt++) {
        rowA[mt] = wm * 32 + mt * 16 + arowoff;
        swA[mt]  = (rowA[mt] >> 1) & 3;
    }
    int rowB[4], swB[4];
    #pragma unroll
    for (int nt2 = 0; nt2 < 4; nt2++) {
        rowB[nt2] = wn * 64 + nt2 * 16 + browoff;
        swB[nt2]  = (rowB[nt2] >> 1) & 3;
    }

    if (F > 0) load_flat(0);
    if (F > 1) load_flat(1);

    int f = 0;
    for (int tile = blockIdx.x; tile < ntile; tile += gridDim.x) {
        const int m0 = (tile / nx) << 7, n0 = (tile % nx) << 7;

        float acc[2][8][4];
        #pragma unroll
        for (int mt = 0; mt < 2; mt++)
            #pragma unroll
            for (int nt = 0; nt < 8; nt++)
                #pragma unroll
                for (int q = 0; q < 4; q++) acc[mt][nt][q] = 0.f;

        for (int c = 0; c < NCH; c++, f++) {
            if (f + 1 < F) { CP_WAIT1(); } else { CP_WAIT0(); }
            __syncthreads();
            if (f + 2 < F) load_flat(f + 2);

            const uint32_t st = sbase + (uint32_t)(f % 3) * STAGE_B;
            #pragma unroll
            for (int s = 0; s < 2; s++) {
                uint32_t ahi[2][4], alo[2][4];
                #pragma unroll
                for (int mt = 0; mt < 2; mt++) {
                    uint32_t off = (uint32_t)(rowA[mt] * 64 + (((2*s + akoff) ^ swA[mt]) * 16));
                    ldsm4(ahi[mt], st + off);
                    ldsm4(alo[mt], st + TILE_B + off);
                }
                uint32_t bhi[4][4], blo[4][4];
                #pragma unroll
                for (int nt2 = 0; nt2 < 4; nt2++) {
                    uint32_t off = (uint32_t)(rowB[nt2] * 64 + (((2*s + bkoff) ^ swB[nt2]) * 16));
                    ldsm4(bhi[nt2], st + 2*TILE_B + off);
                    ldsm4(blo[nt2], st + 3*TILE_B + off);
                }
                #pragma unroll
                for (int mt = 0; mt < 2; mt++)
                    #pragma unroll
                    for (int nt = 0; nt < 8; nt++) {
                        const uint32_t* bh = &bhi[nt >> 1][(nt & 1) * 2];
                        const uint32_t* bl = &blo[nt >> 1][(nt & 1) * 2];
                        mma_bf16(acc[mt][nt], ahi[mt], bh);
                        mma_bf16(acc[mt][nt], ahi[mt], bl);
                        mma_bf16(acc[mt][nt], alo[mt], bh);
                    }
            }
        }

        const int lr = lane >> 2, lc = (lane & 3) * 2;
        #pragma unroll
        for (int mt = 0; mt < 2; mt++) {
            #pragma unroll
            for (int half = 0; half < 2; half++) {
                const int m = m0 + wm * 32 + mt * 16 + lr + half * 8;
                #pragma unroll
                for (int nt = 0; nt < 8; nt++) {
                    const int n = n0 + wn * 64 + nt * 8 + lc;
                    float rx = acc[mt][nt][half * 2 + 0] + bias[n + 0];
                    float ry = acc[mt][nt][half * 2 + 1] + bias[n + 1];
                    if (!SCATTER) {
                        *(float2*)&C[(size_t)m * N + n] = make_float2(rx, ry);
                    } else {
                        int mat = n >> 10, h = (n >> 6) & 15, d = n & 63;
                        int b = m >> 11, t = m & 2047;
                        if (mat == 0) { rx *= 0.125f; ry *= 0.125f; }
                        __nv_bfloat16 hx = __float2bfloat16(rx), hy = __float2bfloat16(ry);
                        __nv_bfloat16* dh = (mat == 0) ? (__nv_bfloat16*)g_qhi
                                           : (mat == 1) ? (__nv_bfloat16*)g_khi : (__nv_bfloat16*)g_vhi;
                        size_t off = (((size_t)(b * NH + h) * TSEQ) + t) * HD + d;
                        *(ushort2*)&dh[off] = make_ushort2(bfbits(hx), bfbits(hy));
                        if (mat != 0) {
                            unsigned short lx = bfbits(__float2bfloat16(rx - __bfloat162float(hx)));
                            unsigned short ly = bfbits(__float2bfloat16(ry - __bfloat162float(hy)));
                            __nv_bfloat16* dl = (mat == 1) ? (__nv_bfloat16*)g_klo : (__nv_bfloat16*)g_vlo;
                            *(ushort2*)&dl[off] = make_ushort2(lx, ly);
                        }
                    }
                }
            }
        }
    }
}

// ---------------- flash attention, 3-stage KV, 2 CTAs/SM ----------------
#define FL_QHI 0u
#define FL_STG 16384u
#define FL_SSZ 32768u
#define FL_SMEM (FL_STG + 3 * FL_SSZ)   // 114688; x2 CTAs fits 228KB

__global__ __launch_bounds__(256, 2)
void flash_mma(const __nv_bfloat16* __restrict__ qhi,
               const __nv_bfloat16* __restrict__ khi, const __nv_bfloat16* __restrict__ klo,
               const __nv_bfloat16* __restrict__ vhi, const __nv_bfloat16* __restrict__ vlo,
               __nv_bfloat16* __restrict__ ohi, __nv_bfloat16* __restrict__ olo)
{
    extern __shared__ char smem[];
    const uint32_t sb = smem_u32(smem);
    const int tid = threadIdx.x, wid = tid >> 5, lane = tid & 31;
    const int bh = blockIdx.y;
    const int qb = gridDim.x - 1 - blockIdx.x;     // heavy tiles first
    const int qbase = qb * 128;
    const size_t base = (size_t)bh * TSEQ * HD;
    const int nkb = 2 * qb + 2;

    auto ldq = [&]() {
        #pragma unroll
        for (int t = 0; t < 4; t++) {
            int idx = tid + t * 256;
            int row = idx >> 3, ch = idx & 7;
            uint32_t so = (uint32_t)(row * 128 + ((ch ^ (row & 7)) * 16));
            size_t g = base + (size_t)(qbase + row) * HD + ch * 8;
            cpasync16(sb + FL_QHI + so, qhi + g);
        }
    };
    auto ldkv = [&](int kb) {
        const uint32_t st = sb + FL_STG + (uint32_t)(kb % 3) * FL_SSZ;
        #pragma unroll
        for (int t = 0; t < 2; t++) {
            int idx = tid + t * 256;
            int row = idx >> 3, ch = idx & 7;
            uint32_t so = (uint32_t)(row * 128 + ((ch ^ (row & 7)) * 16));
            size_t g = base + (size_t)(kb * 64 + row) * HD + ch * 8;
            cpasync16(st + so,          khi + g);
            cpasync16(st + 8192 + so,   klo + g);
            cpasync16(st + 16384 + so,  vhi + g);
            cpasync16(st + 24576 + so,  vlo + g);
        }
        CP_COMMIT();
    };

    ldq();
    ldkv(0);
    if (nkb > 1) ldkv(1);

    const int arow = wid * 16 + (lane & 15);
    const int akoff = lane >> 4;
    const int brow_off = (lane & 7) + ((lane >> 4) << 3);
    const int bkoff = (lane >> 3) & 1;
    const int vrow_off = (lane & 7) + (((lane >> 3) & 1) << 3);
    const int vcg = lane >> 4;

    uint32_t qh[4][4];
    float acc_o[8][4];
    #pragma unroll
    for (int nt = 0; nt < 8; nt++)
        #pragma unroll
        for (int q = 0; q < 4; q++) acc_o[nt][q] = 0.f;
    float m0 = -1e30f, m1 = -1e30f, l0 = 0.f, l1 = 0.f;

    const int r0g = qbase + wid * 16 + (lane >> 2);
    const int r1g = r0g + 8;

    for (int kb = 0; kb < nkb; kb++) {
        if (kb + 1 < nkb) { CP_WAIT1(); } else { CP_WAIT0(); }
        __syncthreads();
        if (kb + 2 < nkb) ldkv(kb + 2);

        if (kb == 0) {
            #pragma unroll
            for (int s4 = 0; s4 < 4; s4++) {
                uint32_t off = (uint32_t)(arow * 128 + (((2*s4 + akoff) ^ (arow & 7)) * 16));
                ldsm4(qh[s4], sb + FL_QHI + off);
            }
        }

        const uint32_t st = sb + FL_STG + (uint32_t)(kb % 3) * FL_SSZ;

        float s[8][4];
        #pragma unroll
        for (int nt = 0; nt < 8; nt++)
            #pragma unroll
            for (int q = 0; q < 4; q++) s[nt][q] = 0.f;

        // S = Q K^T (2-pass), K fragments loaded just-in-time per nt2 (low regs)
        #pragma unroll
        for (int s4 = 0; s4 < 4; s4++) {
            #pragma unroll
            for (int nt2 = 0; nt2 < 4; nt2++) {
                int row = nt2 * 16 + brow_off;
                uint32_t off = (uint32_t)(row * 128 + (((2*s4 + bkoff) ^ (row & 7)) * 16));
                uint32_t kh[4], kl[4];
                ldsm4(kh, st + off);
                ldsm4(kl, st + 8192 + off);
                mma_bf16(s[2*nt2],     qh[s4], &kh[0]);
                mma_bf16(s[2*nt2],     qh[s4], &kl[0]);
                mma_bf16(s[2*nt2 + 1], qh[s4], &kh[2]);
                mma_bf16(s[2*nt2 + 1], qh[s4], &kl[2]);
            }
        }

        const int kbase = kb * 64;
        if (kb >= nkb - 2) {
            #pragma unroll
            for (int nt = 0; nt < 8; nt++) {
                int kg0 = kbase + nt * 8 + 2 * (lane & 3);
                if (kg0 > r0g)     s[nt][0] = -1e30f;
                if (kg0 + 1 > r0g) s[nt][1] = -1e30f;
                if (kg0 > r1g)     s[nt][2] = -1e30f;
                if (kg0 + 1 > r1g) s[nt][3] = -1e30f;
            }
        }

        float mx0 = -1e30f, mx1 = -1e30f;
        #pragma unroll
        for (int nt = 0; nt < 8; nt++) {
            mx0 = fmaxf(mx0, fmaxf(s[nt][0], s[nt][1]));
            mx1 = fmaxf(mx1, fmaxf(s[nt][2], s[nt][3]));
        }
        mx0 = fmaxf(mx0, __shfl_xor_sync(0xffffffffu, mx0, 1));
        mx0 = fmaxf(mx0, __shfl_xor_sync(0xffffffffu, mx0, 2));
        mx1 = fmaxf(mx1, __shfl_xor_sync(0xffffffffu, mx1, 1));
        mx1 = fmaxf(mx1, __shfl_xor_sync(0xffffffffu, mx1, 2));
        float mn0 = fmaxf(m0, mx0), mn1 = fmaxf(m1, mx1);
        float a0 = __expf(m0 - mn0), a1 = __expf(m1 - mn1);
        float sum0 = 0.f, sum1 = 0.f;
        #pragma unroll
        for (int nt = 0; nt < 8; nt++) {
            s[nt][0] = __expf(s[nt][0] - mn0);
            s[nt][1] = __expf(s[nt][1] - mn0);
            s[nt][2] = __expf(s[nt][2] - mn1);
            s[nt][3] = __expf(s[nt][3] - mn1);
            sum0 += s[nt][0] + s[nt][1];
            sum1 += s[nt][2] + s[nt][3];
        }
        sum0 += __shfl_xor_sync(0xffffffffu, sum0, 1);
        sum0 += __shfl_xor_sync(0xffffffffu, sum0, 2);
        sum1 += __shfl_xor_sync(0xffffffffu, sum1, 1);
        sum1 += __shfl_xor_sync(0xffffffffu, sum1, 2);
        l0 = l0 * a0 + sum0; m0 = mn0;
        l1 = l1 * a1 + sum1; m1 = mn1;
        #pragma unroll
        for (int nt = 0; nt < 8; nt++) {
            acc_o[nt][0] *= a0; acc_o[nt][1] *= a0;
            acc_o[nt][2] *= a1; acc_o[nt][3] *= a1;
        }

        // P fragments (hi/lo), overwriting s's live range
        uint32_t phi[4][4], plo[4][4];
        #pragma unroll
        for (int j2 = 0; j2 < 4; j2++) {
            float r0a, r0b, r1a, r1b, r2a, r2b, r3a, r3b;
            phi[j2][0] = pack_hilo(s[2*j2][0],   s[2*j2][1],   &r0a, &r0b);
            phi[j2][1] = pack_hilo(s[2*j2][2],   s[2*j2][3],   &r1a, &r1b);
            phi[j2][2] = pack_hilo(s[2*j2+1][0], s[2*j2+1][1], &r2a, &r2b);
            phi[j2][3] = pack_hilo(s[2*j2+1][2], s[2*j2+1][3], &r3a, &r3b);
            plo[j2][0] = pack_bf(r0a, r0b);
            plo[j2][1] = pack_bf(r1a, r1b);
            plo[j2][2] = pack_bf(r2a, r2b);
            plo[j2][3] = pack_bf(r3a, r3b);
        }

        #pragma unroll
        for (int j2 = 0; j2 < 4; j2++) {
            int vrow = j2 * 16 + vrow_off;
            #pragma unroll
            for (int g = 0; g < 4; g++) {
                int cg = g * 2 + vcg;
                uint32_t off = (uint32_t)(vrow * 128 + ((cg ^ (vrow & 7)) * 16));
                uint32_t vh[4], vl[4];
                ldsm4t(vh, st + 16384 + off);
                ldsm4t(vl, st + 24576 + off);
                mma_bf16(acc_o[2*g],     phi[j2], &vh[0]);
                mma_bf16(acc_o[2*g],     phi[j2], &vl[0]);
                mma_bf16(acc_o[2*g],     plo[j2], &vh[0]);
                mma_bf16(acc_o[2*g + 1], phi[j2], &vh[2]);
                mma_bf16(acc_o[2*g + 1], phi[j2], &vl[2]);
                mma_bf16(acc_o[2*g + 1], plo[j2], &vh[2]);
            }
        }
    }

    const int b = bh >> 4, h = bh & 15;
    const float inv0 = 1.f / l0, inv1 = 1.f / l1;
    #pragma unroll
    for (int nt = 0; nt < 8; nt++) {
        int d = nt * 8 + 2 * (lane & 3);
        float f0 = acc_o[nt][0] * inv0, f1 = acc_o[nt][1] * inv0;
        float f2 = acc_o[nt][2] * inv1, f3 = acc_o[nt][3] * inv1;
        size_t o0 = ((size_t)(b * TSEQ + r0g)) * DM + h * HD + d;
        size_t o1 = ((size_t)(b * TSEQ + r1g)) * DM + h * HD + d;
        __nv_bfloat16 h0 = __float2bfloat16(f0), h1 = __float2bfloat16(f1);
        __nv_bfloat16 h2 = __float2bfloat16(f2), h3 = __float2bfloat16(f3);
        *(ushort2*)&ohi[o0] = make_ushort2(bfbits(h0), bfbits(h1));
        *(ushort2*)&ohi[o1] = make_ushort2(bfbits(h2), bfbits(h3));
        *(ushort2*)&olo[o0] = make_ushort2(
            bfbits(__float2bfloat16(f0 - __bfloat162float(h0))),
            bfbits(__float2bfloat16(f1 - __bfloat162float(h1))));
        *(ushort2*)&olo[o1] = make_ushort2(
            bfbits(__float2bfloat16(f2 - __bfloat162float(h2))),
            bfbits(__float2bfloat16(f3 - __bfloat162float(h3))));
    }
}

// ---------------------------------------------------------------------------
extern "C" void kernel_launch(void* const* d_in, const int* in_sizes, int n_in,
                              void* d_out, int out_size)
{
    (void)in_sizes; (void)n_in; (void)out_size;
    const float* x     = (const float*)d_in[0];
    const float* qkv_w = (const float*)d_in[1];
    const float* qkv_b = (const float*)d_in[2];
    const float* out_w = (const float*)d_in[3];
    const float* out_b = (const float*)d_in[4];
    float* out = (float*)d_out;

    __nv_bfloat16 *xhi, *xlo, *w1hi, *w1lo, *w2hi, *w2lo, *ahi, *alo;
    __nv_bfloat16 *qhi, *khi, *klo, *vhi, *vlo;
    cudaGetSymbolAddress((void**)&xhi,  g_xhi);  cudaGetSymbolAddress((void**)&xlo,  g_xlo);
    cudaGetSymbolAddress((void**)&w1hi, g_w1hi); cudaGetSymbolAddress((void**)&w1lo, g_w1lo);
    cudaGetSymbolAddress((void**)&w2hi, g_w2hi); cudaGetSymbolAddress((void**)&w2lo, g_w2lo);
    cudaGetSymbolAddress((void**)&ahi,  g_ahi);  cudaGetSymbolAddress((void**)&alo,  g_alo);
    cudaGetSymbolAddress((void**)&qhi,  g_qhi);
    cudaGetSymbolAddress((void**)&khi,  g_khi);  cudaGetSymbolAddress((void**)&klo,  g_klo);
    cudaGetSymbolAddress((void**)&vhi,  g_vhi);  cudaGetSymbolAddress((void**)&vlo,  g_vlo);

    cudaFuncSetAttribute(mma_gemm<true>,  cudaFuncAttributeMaxDynamicSharedMemorySize, GEMM_SMEM);
    cudaFuncSetAttribute(mma_gemm<false>, cudaFuncAttributeMaxDynamicSharedMemorySize, GEMM_SMEM);
    cudaFuncSetAttribute(flash_mma, cudaFuncAttributeMaxDynamicSharedMemorySize, FL_SMEM);

    // 0) fused bf16 hi/lo splits
    split3_kernel<<<(SPLIT_TOT + 255)/256, 256>>>(x, qkv_w, out_w);

    // 1) QKV projection (persistent, 3-stage)
    {
        int ntile = (MTOT/128) * (3*DM/128);
        int grid = ntile < 296 ? ntile : 296;
        mma_gemm<true><<<grid, 256, GEMM_SMEM>>>(xhi, xlo, w1hi, w1lo, qkv_b, nullptr, 3*DM);
    }

    // 2) flash attention (3-stage KV, 2 CTAs/SM)
    dim3 g2(TSEQ/128, BDIM*NH);
    flash_mma<<<g2, 256, FL_SMEM>>>(qhi, khi, klo, vhi, vlo, ahi, alo);

    // 3) output projection (persistent, 3-stage)
    {
        int ntile = (MTOT/128) * (DM/128);
        int grid = ntile < 296 ? ntile : 296;
        mma_gemm<false><<<grid, 256, GEMM_SMEM>>>(ahi, alo, w2hi, w2lo, out_b, out, DM);
    }
}

// round 9
// speedup vs baseline: 1.4022x; 1.4022x over previous
#include <cuda_runtime.h>
#include <cuda_fp16.h>
#include <cstdint>

#define BDIM 2
#define TSEQ 2048
#define NH 16
#define HD 64
#define DM 1024
#define MTOT (BDIM*TSEQ)

// ---------------- scratch (allocation-free: __device__ globals) ----------------
__device__ uint4 g_xhi[(size_t)MTOT*DM*2/16];
__device__ uint4 g_w1hi[(size_t)3*DM*DM*2/16], g_w1lo[(size_t)3*DM*DM*2/16];
__device__ uint4 g_w2hi[(size_t)DM*DM*2/16],   g_w2lo[(size_t)DM*DM*2/16];
__device__ uint4 g_qhi[(size_t)BDIM*NH*TSEQ*HD*2/16];
__device__ uint4 g_khi[(size_t)BDIM*NH*TSEQ*HD*2/16], g_klo[(size_t)BDIM*NH*TSEQ*HD*2/16];
__device__ uint4 g_vhi[(size_t)BDIM*NH*TSEQ*HD*2/16], g_vlo[(size_t)BDIM*NH*TSEQ*HD*2/16];
__device__ uint4 g_ahi[(size_t)MTOT*DM*2/16];

// ---------------- helpers ----------------
__device__ __forceinline__ uint32_t smem_u32(const void* p) {
    uint32_t a;
    asm("{ .reg .u64 t; cvta.to.shared.u64 t, %1; cvt.u32.u64 %0, t; }" : "=r"(a) : "l"(p));
    return a;
}
__device__ __forceinline__ void cpasync16(uint32_t dst, const void* src) {
    asm volatile("cp.async.cg.shared.global [%0], [%1], 16;" :: "r"(dst), "l"(src) : "memory");
}
#define CP_COMMIT() asm volatile("cp.async.commit_group;" ::: "memory")
#define CP_WAIT1()  asm volatile("cp.async.wait_group 1;" ::: "memory")
#define CP_WAIT0()  asm volatile("cp.async.wait_group 0;" ::: "memory")
__device__ __forceinline__ void ldsm4(uint32_t* r, uint32_t addr) {
    asm volatile("ldmatrix.sync.aligned.m8n8.x4.shared.b16 {%0,%1,%2,%3}, [%4];"
        : "=r"(r[0]), "=r"(r[1]), "=r"(r[2]), "=r"(r[3]) : "r"(addr));
}
__device__ __forceinline__ void ldsm4t(uint32_t* r, uint32_t addr) {
    asm volatile("ldmatrix.sync.aligned.m8n8.x4.trans.shared.b16 {%0,%1,%2,%3}, [%4];"
        : "=r"(r[0]), "=r"(r[1]), "=r"(r[2]), "=r"(r[3]) : "r"(addr));
}
__device__ __forceinline__ void mma_f16(float* c, const uint32_t* a, const uint32_t* b) {
    asm volatile(
        "mma.sync.aligned.m16n8k16.row.col.f32.f16.f16.f32 "
        "{%0,%1,%2,%3}, {%4,%5,%6,%7}, {%8,%9}, {%0,%1,%2,%3};"
        : "+f"(c[0]), "+f"(c[1]), "+f"(c[2]), "+f"(c[3])
        : "r"(a[0]), "r"(a[1]), "r"(a[2]), "r"(a[3]), "r"(b[0]), "r"(b[1]));
}
__device__ __forceinline__ unsigned short hbits(__half h) {
    return reinterpret_cast<unsigned short&>(h);
}
__device__ __forceinline__ uint32_t pack_h2(float a, float b) {
    __half2 h = __floats2half2_rn(a, b);
    return reinterpret_cast<uint32_t&>(h);
}

// ---------------- fused fp32 -> fp16 hi(/lo) split over 3 tensors ----------------
#define SPLIT_N0 (MTOT*DM/4)
#define SPLIT_N1 (3*DM*DM/4)
#define SPLIT_N2 (DM*DM/4)
#define SPLIT_TOT (SPLIT_N0 + SPLIT_N1 + SPLIT_N2)

__global__ __launch_bounds__(256)
void split3_kernel(const float* __restrict__ s0, const float* __restrict__ s1,
                   const float* __restrict__ s2)
{
    int i = blockIdx.x * blockDim.x + threadIdx.x;
    if (i >= SPLIT_TOT) return;
    const float* s; __half *hi, *lo; int j;
    if (i < SPLIT_N0) {
        s = s0; hi = (__half*)g_xhi; lo = nullptr; j = i;
    } else if (i < SPLIT_N0 + SPLIT_N1) {
        s = s1; hi = (__half*)g_w1hi; lo = (__half*)g_w1lo; j = i - SPLIT_N0;
    } else {
        s = s2; hi = (__half*)g_w2hi; lo = (__half*)g_w2lo; j = i - SPLIT_N0 - SPLIT_N1;
    }
    float4 v = ((const float4*)s)[j];
    float f[4] = {v.x, v.y, v.z, v.w};
    unsigned short h[4], l[4];
    #pragma unroll
    for (int k = 0; k < 4; k++) {
        __half hb = __float2half_rn(f[k]);
        h[k] = hbits(hb);
        l[k] = hbits(__float2half_rn(f[k] - __half2float(hb)));
    }
    ((ushort4*)hi)[j] = make_ushort4(h[0], h[1], h[2], h[3]);
    if (lo) ((ushort4*)lo)[j] = make_ushort4(l[0], l[1], l[2], l[3]);
}

// ---------------- persistent mma.sync GEMM, fp16 2-pass: C = Ahi*(Whi+Wlo) + bias ---
#define BK 32
#define NCH (DM / BK)
#define TILE_B 8192
#define STAGE_B (3 * TILE_B)        // Ahi, Whi, Wlo
#define GEMM_SMEM (2 * STAGE_B)     // 49152

template<bool SCATTER>
__global__ __launch_bounds__(256, 2)
void mma_gemm(const __half* __restrict__ Ahi,
              const __half* __restrict__ Whi, const __half* __restrict__ Wlo,
              const float* __restrict__ bias, float* __restrict__ C, int N)
{
    extern __shared__ char smem[];
    const uint32_t sbase = smem_u32(smem);
    const int tid = threadIdx.x, wid = tid >> 5, lane = tid & 31;
    const int wm = wid & 3, wn = wid >> 2;
    const int K = DM;
    const int nx = N >> 7;
    const int ntile = (MTOT >> 7) * nx;

    auto load_stage = [&](int m0, int n0, int c, int stg) {
        const uint32_t st = sbase + (uint32_t)stg * STAGE_B;
        const int k0 = c * BK;
        #pragma unroll
        for (int t = 0; t < 2; t++) {
            int idx = tid + t * 256;
            int row = idx >> 2, ch = idx & 3;
            uint32_t so = (uint32_t)(row * 64 + ((ch ^ ((row >> 1) & 3)) * 16));
            int gk = k0 + ch * 8;
            const size_t ea = (size_t)(m0 + row) * K + gk;
            const size_t ew = (size_t)(n0 + row) * K + gk;
            cpasync16(st + so,              Ahi + ea);
            cpasync16(st + TILE_B + so,     Whi + ew);
            cpasync16(st + 2*TILE_B + so,   Wlo + ew);
        }
        CP_COMMIT();
    };

    const int arowoff = lane & 15;
    const int akoff   = lane >> 4;
    const int browoff = (lane & 7) + ((lane >> 4) << 3);
    const int bkoff   = (lane >> 3) & 1;

    int rowA[2], swA[2];
    #pragma unroll
    for (int mt = 0; mt < 2; mt++) {
        rowA[mt] = wm * 32 + mt * 16 + arowoff;
        swA[mt]  = (rowA[mt] >> 1) & 3;
    }
    int rowB[4], swB[4];
    #pragma unroll
    for (int nt2 = 0; nt2 < 4; nt2++) {
        rowB[nt2] = wn * 64 + nt2 * 16 + browoff;
        swB[nt2]  = (rowB[nt2] >> 1) & 3;
    }

    // prime: first tile's chunk 0
    {
        int t0 = blockIdx.x;
        if (t0 < ntile) load_stage((t0 / nx) << 7, (t0 % nx) << 7, 0, 0);
    }

    for (int tile = blockIdx.x; tile < ntile; tile += gridDim.x) {
        const int m0 = (tile / nx) << 7, n0 = (tile % nx) << 7;
        const int tnext = tile + gridDim.x;
        const bool has_next = tnext < ntile;
        const int mn = has_next ? ((tnext / nx) << 7) : 0;
        const int nn = has_next ? ((tnext % nx) << 7) : 0;

        float acc[2][8][4];
        #pragma unroll
        for (int mt = 0; mt < 2; mt++)
            #pragma unroll
            for (int nt = 0; nt < 8; nt++)
                #pragma unroll
                for (int q = 0; q < 4; q++) acc[mt][nt][q] = 0.f;

        for (int c = 0; c < NCH; c++) {
            const int cur = c & 1;
            if (c + 1 < NCH) {
                load_stage(m0, n0, c + 1, cur ^ 1);
                CP_WAIT1();
            } else if (has_next) {
                load_stage(mn, nn, 0, 0);   // (NCH-1)&1 ^ 1 == 0
                CP_WAIT1();
            } else {
                CP_WAIT0();
            }
            __syncthreads();

            const uint32_t st = sbase + (uint32_t)cur * STAGE_B;
            #pragma unroll
            for (int s = 0; s < 2; s++) {
                uint32_t ahi[2][4];
                #pragma unroll
                for (int mt = 0; mt < 2; mt++) {
                    uint32_t off = (uint32_t)(rowA[mt] * 64 + (((2*s + akoff) ^ swA[mt]) * 16));
                    ldsm4(ahi[mt], st + off);
                }
                uint32_t bhi[4][4], blo[4][4];
                #pragma unroll
                for (int nt2 = 0; nt2 < 4; nt2++) {
                    uint32_t off = (uint32_t)(rowB[nt2] * 64 + (((2*s + bkoff) ^ swB[nt2]) * 16));
                    ldsm4(bhi[nt2], st + TILE_B + off);
                    ldsm4(blo[nt2], st + 2*TILE_B + off);
                }
                #pragma unroll
                for (int mt = 0; mt < 2; mt++)
                    #pragma unroll
                    for (int nt = 0; nt < 8; nt++) {
                        const uint32_t* bh = &bhi[nt >> 1][(nt & 1) * 2];
                        const uint32_t* bl = &blo[nt >> 1][(nt & 1) * 2];
                        mma_f16(acc[mt][nt], ahi[mt], bh);
                        mma_f16(acc[mt][nt], ahi[mt], bl);
                    }
            }
            __syncthreads();
        }

        const int lr = lane >> 2, lc = (lane & 3) * 2;
        #pragma unroll
        for (int mt = 0; mt < 2; mt++) {
            #pragma unroll
            for (int half = 0; half < 2; half++) {
                const int m = m0 + wm * 32 + mt * 16 + lr + half * 8;
                #pragma unroll
                for (int nt = 0; nt < 8; nt++) {
                    const int n = n0 + wn * 64 + nt * 8 + lc;
                    float rx = acc[mt][nt][half * 2 + 0] + bias[n + 0];
                    float ry = acc[mt][nt][half * 2 + 1] + bias[n + 1];
                    if (!SCATTER) {
                        *(float2*)&C[(size_t)m * N + n] = make_float2(rx, ry);
                    } else {
                        int mat = n >> 10, h = (n >> 6) & 15, d = n & 63;
                        int b = m >> 11, t = m & 2047;
                        if (mat == 0) { rx *= 0.125f; ry *= 0.125f; }
                        __half hx = __float2half_rn(rx), hy = __float2half_rn(ry);
                        __half* dh = (mat == 0) ? (__half*)g_qhi
                                    : (mat == 1) ? (__half*)g_khi : (__half*)g_vhi;
                        size_t off = (((size_t)(b * NH + h) * TSEQ) + t) * HD + d;
                        *(ushort2*)&dh[off] = make_ushort2(hbits(hx), hbits(hy));
                        if (mat != 0) {
                            unsigned short lx = hbits(__float2half_rn(rx - __half2float(hx)));
                            unsigned short ly = hbits(__float2half_rn(ry - __half2float(hy)));
                            __half* dl = (mat == 1) ? (__half*)g_klo : (__half*)g_vlo;
                            *(ushort2*)&dl[off] = make_ushort2(lx, ly);
                        }
                    }
                }
            }
        }
    }
}

// ---------------- flash attention, fp16: S = Qhi*(Khi+Klo), O = Phi*(Vhi+Vlo) -----
#define FL_QHI 0u
#define FL_STG 16384u
#define FL_SSZ 32768u
#define FL_SMEM (FL_STG + 2 * FL_SSZ)   // 81920

__global__ __launch_bounds__(256, 1)
void flash_mma(const __half* __restrict__ qhi,
               const __half* __restrict__ khi, const __half* __restrict__ klo,
               const __half* __restrict__ vhi, const __half* __restrict__ vlo,
               __half* __restrict__ ohi)
{
    extern __shared__ char smem[];
    const uint32_t sb = smem_u32(smem);
    const int tid = threadIdx.x, wid = tid >> 5, lane = tid & 31;
    const int bh = blockIdx.y;
    const int qb = gridDim.x - 1 - blockIdx.x;     // heavy tiles first
    const int qbase = qb * 128;
    const size_t base = (size_t)bh * TSEQ * HD;
    const int nkb = 2 * qb + 2;

    auto ldq = [&]() {
        #pragma unroll
        for (int t = 0; t < 4; t++) {
            int idx = tid + t * 256;
            int row = idx >> 3, ch = idx & 7;
            uint32_t so = (uint32_t)(row * 128 + ((ch ^ (row & 7)) * 16));
            size_t g = base + (size_t)(qbase + row) * HD + ch * 8;
            cpasync16(sb + FL_QHI + so, qhi + g);
        }
    };
    auto ldkv = [&](int kb, int stg) {
        const uint32_t st = sb + FL_STG + (uint32_t)stg * FL_SSZ;
        #pragma unroll
        for (int t = 0; t < 2; t++) {
            int idx = tid + t * 256;
            int row = idx >> 3, ch = idx & 7;
            uint32_t so = (uint32_t)(row * 128 + ((ch ^ (row & 7)) * 16));
            size_t g = base + (size_t)(kb * 64 + row) * HD + ch * 8;
            cpasync16(st + so,          khi + g);
            cpasync16(st + 8192 + so,   klo + g);
            cpasync16(st + 16384 + so,  vhi + g);
            cpasync16(st + 24576 + so,  vlo + g);
        }
        CP_COMMIT();
    };

    ldq();
    ldkv(0, 0);

    const int arow = wid * 16 + (lane & 15);
    const int akoff = lane >> 4;
    const int brow_off = (lane & 7) + ((lane >> 4) << 3);
    const int bkoff = (lane >> 3) & 1;
    const int vrow_off = (lane & 7) + (((lane >> 3) & 1) << 3);
    const int vcg = lane >> 4;

    uint32_t qh[4][4];
    float acc_o[8][4];
    #pragma unroll
    for (int nt = 0; nt < 8; nt++)
        #pragma unroll
        for (int q = 0; q < 4; q++) acc_o[nt][q] = 0.f;
    float m0 = -1e30f, m1 = -1e30f, l0 = 0.f, l1 = 0.f;

    const int r0g = qbase + wid * 16 + (lane >> 2);
    const int r1g = r0g + 8;

    for (int kb = 0; kb < nkb; kb++) {
        const int cur = kb & 1;
        if (kb + 1 < nkb) {
            ldkv(kb + 1, cur ^ 1);
            CP_WAIT1();
        } else {
            CP_WAIT0();
        }
        __syncthreads();

        if (kb == 0) {
            #pragma unroll
            for (int s4 = 0; s4 < 4; s4++) {
                uint32_t off = (uint32_t)(arow * 128 + (((2*s4 + akoff) ^ (arow & 7)) * 16));
                ldsm4(qh[s4], sb + FL_QHI + off);
            }
        }

        const uint32_t st = sb + FL_STG + (uint32_t)cur * FL_SSZ;

        float s[8][4];
        #pragma unroll
        for (int nt = 0; nt < 8; nt++)
            #pragma unroll
            for (int q = 0; q < 4; q++) s[nt][q] = 0.f;

        #pragma unroll
        for (int s4 = 0; s4 < 4; s4++) {
            uint32_t kh[4][4], kl[4][4];
            #pragma unroll
            for (int nt2 = 0; nt2 < 4; nt2++) {
                int row = nt2 * 16 + brow_off;
                uint32_t off = (uint32_t)(row * 128 + (((2*s4 + bkoff) ^ (row & 7)) * 16));
                ldsm4(kh[nt2], st + off);
                ldsm4(kl[nt2], st + 8192 + off);
            }
            #pragma unroll
            for (int nt = 0; nt < 8; nt++) {
                const uint32_t* bh_ = &kh[nt >> 1][(nt & 1) * 2];
                const uint32_t* bl_ = &kl[nt >> 1][(nt & 1) * 2];
                mma_f16(s[nt], qh[s4], bh_);
                mma_f16(s[nt], qh[s4], bl_);
            }
        }

        const int kbase = kb * 64;
        if (kb >= nkb - 2) {
            #pragma unroll
            for (int nt = 0; nt < 8; nt++) {
                int kg0 = kbase + nt * 8 + 2 * (lane & 3);
                if (kg0 > r0g)     s[nt][0] = -1e30f;
                if (kg0 + 1 > r0g) s[nt][1] = -1e30f;
                if (kg0 > r1g)     s[nt][2] = -1e30f;
                if (kg0 + 1 > r1g) s[nt][3] = -1e30f;
            }
        }

        float mx0 = -1e30f, mx1 = -1e30f;
        #pragma unroll
        for (int nt = 0; nt < 8; nt++) {
            mx0 = fmaxf(mx0, fmaxf(s[nt][0], s[nt][1]));
            mx1 = fmaxf(mx1, fmaxf(s[nt][2], s[nt][3]));
        }
        mx0 = fmaxf(mx0, __shfl_xor_sync(0xffffffffu, mx0, 1));
        mx0 = fmaxf(mx0, __shfl_xor_sync(0xffffffffu, mx0, 2));
        mx1 = fmaxf(mx1, __shfl_xor_sync(0xffffffffu, mx1, 1));
        mx1 = fmaxf(mx1, __shfl_xor_sync(0xffffffffu, mx1, 2));
        float mn0 = fmaxf(m0, mx0), mn1 = fmaxf(m1, mx1);
        float a0 = __expf(m0 - mn0), a1 = __expf(m1 - mn1);
        float sum0 = 0.f, sum1 = 0.f;
        #pragma unroll
        for (int nt = 0; nt < 8; nt++) {
            s[nt][0] = __expf(s[nt][0] - mn0);
            s[nt][1] = __expf(s[nt][1] - mn0);
            s[nt][2] = __expf(s[nt][2] - mn1);
            s[nt][3] = __expf(s[nt][3] - mn1);
            sum0 += s[nt][0] + s[nt][1];
            sum1 += s[nt][2] + s[nt][3];
        }
        sum0 += __shfl_xor_sync(0xffffffffu, sum0, 1);
        sum0 += __shfl_xor_sync(0xffffffffu, sum0, 2);
        sum1 += __shfl_xor_sync(0xffffffffu, sum1, 1);
        sum1 += __shfl_xor_sync(0xffffffffu, sum1, 2);
        l0 = l0 * a0 + sum0; m0 = mn0;
        l1 = l1 * a1 + sum1; m1 = mn1;
        #pragma unroll
        for (int nt = 0; nt < 8; nt++) {
            acc_o[nt][0] *= a0; acc_o[nt][1] *= a0;
            acc_o[nt][2] *= a1; acc_o[nt][3] *= a1;
        }

        // P fragments (fp16 hi only)
        uint32_t phi[4][4];
        #pragma unroll
        for (int j2 = 0; j2 < 4; j2++) {
            phi[j2][0] = pack_h2(s[2*j2][0],   s[2*j2][1]);
            phi[j2][1] = pack_h2(s[2*j2][2],   s[2*j2][3]);
            phi[j2][2] = pack_h2(s[2*j2+1][0], s[2*j2+1][1]);
            phi[j2][3] = pack_h2(s[2*j2+1][2], s[2*j2+1][3]);
        }

        // acc_o += Phi @ (Vhi + Vlo)
        #pragma unroll
        for (int j2 = 0; j2 < 4; j2++) {
            int vrow = j2 * 16 + vrow_off;
            #pragma unroll
            for (int g = 0; g < 4; g++) {
                int cg = g * 2 + vcg;
                uint32_t off = (uint32_t)(vrow * 128 + ((cg ^ (vrow & 7)) * 16));
                uint32_t vh[4], vl[4];
                ldsm4t(vh, st + 16384 + off);
                ldsm4t(vl, st + 24576 + off);
                mma_f16(acc_o[2*g],     phi[j2], &vh[0]);
                mma_f16(acc_o[2*g],     phi[j2], &vl[0]);
                mma_f16(acc_o[2*g + 1], phi[j2], &vh[2]);
                mma_f16(acc_o[2*g + 1], phi[j2], &vl[2]);
            }
        }
        __syncthreads();
    }

    const int b = bh >> 4, h = bh & 15;
    const float inv0 = 1.f / l0, inv1 = 1.f / l1;
    #pragma unroll
    for (int nt = 0; nt < 8; nt++) {
        int d = nt * 8 + 2 * (lane & 3);
        size_t o0 = ((size_t)(b * TSEQ + r0g)) * DM + h * HD + d;
        size_t o1 = ((size_t)(b * TSEQ + r1g)) * DM + h * HD + d;
        *(uint32_t*)&ohi[o0] = pack_h2(acc_o[nt][0] * inv0, acc_o[nt][1] * inv0);
        *(uint32_t*)&ohi[o1] = pack_h2(acc_o[nt][2] * inv1, acc_o[nt][3] * inv1);
    }
}

// ---------------------------------------------------------------------------
extern "C" void kernel_launch(void* const* d_in, const int* in_sizes, int n_in,
                              void* d_out, int out_size)
{
    (void)in_sizes; (void)n_in; (void)out_size;
    const float* x     = (const float*)d_in[0];
    const float* qkv_w = (const float*)d_in[1];
    const float* qkv_b = (const float*)d_in[2];
    const float* out_w = (const float*)d_in[3];
    const float* out_b = (const float*)d_in[4];
    float* out = (float*)d_out;

    __half *xhi, *w1hi, *w1lo, *w2hi, *w2lo, *ahi;
    __half *qhi, *khi, *klo, *vhi, *vlo;
    cudaGetSymbolAddress((void**)&xhi,  g_xhi);
    cudaGetSymbolAddress((void**)&w1hi, g_w1hi); cudaGetSymbolAddress((void**)&w1lo, g_w1lo);
    cudaGetSymbolAddress((void**)&w2hi, g_w2hi); cudaGetSymbolAddress((void**)&w2lo, g_w2lo);
    cudaGetSymbolAddress((void**)&ahi,  g_ahi);
    cudaGetSymbolAddress((void**)&qhi,  g_qhi);
    cudaGetSymbolAddress((void**)&khi,  g_khi);  cudaGetSymbolAddress((void**)&klo,  g_klo);
    cudaGetSymbolAddress((void**)&vhi,  g_vhi);  cudaGetSymbolAddress((void**)&vlo,  g_vlo);

    cudaFuncSetAttribute(mma_gemm<true>,  cudaFuncAttributeMaxDynamicSharedMemorySize, GEMM_SMEM);
    cudaFuncSetAttribute(mma_gemm<false>, cudaFuncAttributeMaxDynamicSharedMemorySize, GEMM_SMEM);
    cudaFuncSetAttribute(flash_mma, cudaFuncAttributeMaxDynamicSharedMemorySize, FL_SMEM);

    // 0) fused fp16 splits (x hi-only; weights hi+lo)
    split3_kernel<<<(SPLIT_TOT + 255)/256, 256>>>(x, qkv_w, out_w);

    // 1) QKV projection (persistent) -> fp16 q(hi), k/v(hi,lo) in [B,H,T,Hd]
    {
        int ntile = (MTOT/128) * (3*DM/128);
        int grid = ntile < 296 ? ntile : 296;
        mma_gemm<true><<<grid, 256, GEMM_SMEM>>>(xhi, w1hi, w1lo, qkv_b, nullptr, 3*DM);
    }

    // 2) flash attention -> g_ahi [B,T,D] (fp16)
    dim3 g2(TSEQ/128, BDIM*NH);
    flash_mma<<<g2, 256, FL_SMEM>>>(qhi, khi, klo, vhi, vlo, ahi);

    // 3) output projection (persistent) -> d_out
    {
        int ntile = (MTOT/128) * (DM/128);
        int grid = ntile < 296 ? ntile : 296;
        mma_gemm<false><<<grid, 256, GEMM_SMEM>>>(ahi, w2hi, w2lo, out_b, out, DM);
    }
}

// round 10
// speedup vs baseline: 2.3061x; 1.6446x over previous
#include <cuda_runtime.h>
#include <cuda_fp16.h>
#include <cstdint>

#define BDIM 2
#define TSEQ 2048
#define NH 16
#define HD 64
#define DM 1024
#define MTOT (BDIM*TSEQ)

// ---------------- scratch (allocation-free: __device__ globals) ----------------
__device__ uint4 g_xh[(size_t)MTOT*DM*2/16];
__device__ uint4 g_w1h[(size_t)3*DM*DM*2/16];
__device__ uint4 g_w2h[(size_t)DM*DM*2/16];
__device__ uint4 g_qh[(size_t)BDIM*NH*TSEQ*HD*2/16];
__device__ uint4 g_kh[(size_t)BDIM*NH*TSEQ*HD*2/16];
__device__ uint4 g_vh[(size_t)BDIM*NH*TSEQ*HD*2/16];
__device__ uint4 g_ah[(size_t)MTOT*DM*2/16];

// ---------------- helpers ----------------
__device__ __forceinline__ uint32_t smem_u32(const void* p) {
    uint32_t a;
    asm("{ .reg .u64 t; cvta.to.shared.u64 t, %1; cvt.u32.u64 %0, t; }" : "=r"(a) : "l"(p));
    return a;
}
__device__ __forceinline__ void cpasync16(uint32_t dst, const void* src) {
    asm volatile("cp.async.cg.shared.global [%0], [%1], 16;" :: "r"(dst), "l"(src) : "memory");
}
#define CP_COMMIT() asm volatile("cp.async.commit_group;" ::: "memory")
#define CP_WAIT1()  asm volatile("cp.async.wait_group 1;" ::: "memory")
#define CP_WAIT0()  asm volatile("cp.async.wait_group 0;" ::: "memory")
__device__ __forceinline__ void ldsm4(uint32_t* r, uint32_t addr) {
    asm volatile("ldmatrix.sync.aligned.m8n8.x4.shared.b16 {%0,%1,%2,%3}, [%4];"
        : "=r"(r[0]), "=r"(r[1]), "=r"(r[2]), "=r"(r[3]) : "r"(addr));
}
__device__ __forceinline__ void ldsm4t(uint32_t* r, uint32_t addr) {
    asm volatile("ldmatrix.sync.aligned.m8n8.x4.trans.shared.b16 {%0,%1,%2,%3}, [%4];"
        : "=r"(r[0]), "=r"(r[1]), "=r"(r[2]), "=r"(r[3]) : "r"(addr));
}
__device__ __forceinline__ void mma_f16(float* c, const uint32_t* a, const uint32_t* b) {
    asm volatile(
        "mma.sync.aligned.m16n8k16.row.col.f32.f16.f16.f32 "
        "{%0,%1,%2,%3}, {%4,%5,%6,%7}, {%8,%9}, {%0,%1,%2,%3};"
        : "+f"(c[0]), "+f"(c[1]), "+f"(c[2]), "+f"(c[3])
        : "r"(a[0]), "r"(a[1]), "r"(a[2]), "r"(a[3]), "r"(b[0]), "r"(b[1]));
}
__device__ __forceinline__ unsigned short hbits(__half h) {
    return reinterpret_cast<unsigned short&>(h);
}
__device__ __forceinline__ uint32_t pack_h2(float a, float b) {
    __half2 h = __floats2half2_rn(a, b);
    return reinterpret_cast<uint32_t&>(h);
}

// ---------------- fused fp32 -> fp16 convert over 3 tensors ----------------
#define SPLIT_N0 (MTOT*DM/4)
#define SPLIT_N1 (3*DM*DM/4)
#define SPLIT_N2 (DM*DM/4)
#define SPLIT_TOT (SPLIT_N0 + SPLIT_N1 + SPLIT_N2)

__global__ __launch_bounds__(256)
void cvt3_kernel(const float* __restrict__ s0, const float* __restrict__ s1,
                 const float* __restrict__ s2)
{
    int i = blockIdx.x * blockDim.x + threadIdx.x;
    if (i >= SPLIT_TOT) return;
    const float* s; __half* hi; int j;
    if (i < SPLIT_N0)                  { s = s0; hi = (__half*)g_xh;  j = i; }
    else if (i < SPLIT_N0 + SPLIT_N1)  { s = s1; hi = (__half*)g_w1h; j = i - SPLIT_N0; }
    else                               { s = s2; hi = (__half*)g_w2h; j = i - SPLIT_N0 - SPLIT_N1; }
    float4 v = ((const float4*)s)[j];
    ((uint2*)hi)[j] = make_uint2(pack_h2(v.x, v.y), pack_h2(v.z, v.w));
}

// ---------------- persistent mma.sync GEMM, single-pass fp16 ----------------
#define BK 32
#define NCH (DM / BK)
#define TILE_B 8192
#define STAGE_B (2 * TILE_B)        // A, W
#define GEMM_SMEM (2 * STAGE_B)     // 32768

template<bool SCATTER>
__global__ __launch_bounds__(256, 2)
void mma_gemm(const __half* __restrict__ A, const __half* __restrict__ W,
              const float* __restrict__ bias, float* __restrict__ C, int N)
{
    extern __shared__ char smem[];
    const uint32_t sbase = smem_u32(smem);
    const int tid = threadIdx.x, wid = tid >> 5, lane = tid & 31;
    const int wm = wid & 3, wn = wid >> 2;
    const int K = DM;
    const int nx = N >> 7;
    const int ntile = (MTOT >> 7) * nx;

    auto load_stage = [&](int m0, int n0, int c, int stg) {
        const uint32_t st = sbase + (uint32_t)stg * STAGE_B;
        const int k0 = c * BK;
        #pragma unroll
        for (int t = 0; t < 2; t++) {
            int idx = tid + t * 256;
            int row = idx >> 2, ch = idx & 3;
            uint32_t so = (uint32_t)(row * 64 + ((ch ^ ((row >> 1) & 3)) * 16));
            int gk = k0 + ch * 8;
            cpasync16(st + so,          A + (size_t)(m0 + row) * K + gk);
            cpasync16(st + TILE_B + so, W + (size_t)(n0 + row) * K + gk);
        }
        CP_COMMIT();
    };

    const int arowoff = lane & 15;
    const int akoff   = lane >> 4;
    const int browoff = (lane & 7) + ((lane >> 4) << 3);
    const int bkoff   = (lane >> 3) & 1;

    int rowA[2], swA[2];
    #pragma unroll
    for (int mt = 0; mt < 2; mt++) {
        rowA[mt] = wm * 32 + mt * 16 + arowoff;
        swA[mt]  = (rowA[mt] >> 1) & 3;
    }
    int rowB[4], swB[4];
    #pragma unroll
    for (int nt2 = 0; nt2 < 4; nt2++) {
        rowB[nt2] = wn * 64 + nt2 * 16 + browoff;
        swB[nt2]  = (rowB[nt2] >> 1) & 3;
    }

    {
        int t0 = blockIdx.x;
        if (t0 < ntile) load_stage((t0 / nx) << 7, (t0 % nx) << 7, 0, 0);
    }

    for (int tile = blockIdx.x; tile < ntile; tile += gridDim.x) {
        const int m0 = (tile / nx) << 7, n0 = (tile % nx) << 7;
        const int tnext = tile + gridDim.x;
        const bool has_next = tnext < ntile;
        const int mn = has_next ? ((tnext / nx) << 7) : 0;
        const int nn = has_next ? ((tnext % nx) << 7) : 0;

        float acc[2][8][4];
        #pragma unroll
        for (int mt = 0; mt < 2; mt++)
            #pragma unroll
            for (int nt = 0; nt < 8; nt++)
                #pragma unroll
                for (int q = 0; q < 4; q++) acc[mt][nt][q] = 0.f;

        for (int c = 0; c < NCH; c++) {
            const int cur = c & 1;
            if (c + 1 < NCH) {
                load_stage(m0, n0, c + 1, cur ^ 1);
                CP_WAIT1();
            } else if (has_next) {
                load_stage(mn, nn, 0, 0);
                CP_WAIT1();
            } else {
                CP_WAIT0();
            }
            __syncthreads();

            const uint32_t st = sbase + (uint32_t)cur * STAGE_B;
            #pragma unroll
            for (int s = 0; s < 2; s++) {
                uint32_t ah[2][4];
                #pragma unroll
                for (int mt = 0; mt < 2; mt++) {
                    uint32_t off = (uint32_t)(rowA[mt] * 64 + (((2*s + akoff) ^ swA[mt]) * 16));
                    ldsm4(ah[mt], st + off);
                }
                uint32_t bh[4][4];
                #pragma unroll
                for (int nt2 = 0; nt2 < 4; nt2++) {
                    uint32_t off = (uint32_t)(rowB[nt2] * 64 + (((2*s + bkoff) ^ swB[nt2]) * 16));
                    ldsm4(bh[nt2], st + TILE_B + off);
                }
                #pragma unroll
                for (int mt = 0; mt < 2; mt++)
                    #pragma unroll
                    for (int nt = 0; nt < 8; nt++)
                        mma_f16(acc[mt][nt], ah[mt], &bh[nt >> 1][(nt & 1) * 2]);
            }
            __syncthreads();
        }

        const int lr = lane >> 2, lc = (lane & 3) * 2;
        #pragma unroll
        for (int mt = 0; mt < 2; mt++) {
            #pragma unroll
            for (int half = 0; half < 2; half++) {
                const int m = m0 + wm * 32 + mt * 16 + lr + half * 8;
                #pragma unroll
                for (int nt = 0; nt < 8; nt++) {
                    const int n = n0 + wn * 64 + nt * 8 + lc;
                    float rx = acc[mt][nt][half * 2 + 0] + bias[n + 0];
                    float ry = acc[mt][nt][half * 2 + 1] + bias[n + 1];
                    if (!SCATTER) {
                        *(float2*)&C[(size_t)m * N + n] = make_float2(rx, ry);
                    } else {
                        int mat = n >> 10, h = (n >> 6) & 15, d = n & 63;
                        int b = m >> 11, t = m & 2047;
                        if (mat == 0) { rx *= 0.125f; ry *= 0.125f; }
                        __half* dh = (mat == 0) ? (__half*)g_qh
                                    : (mat == 1) ? (__half*)g_kh : (__half*)g_vh;
                        size_t off = (((size_t)(b * NH + h) * TSEQ) + t) * HD + d;
                        *(uint32_t*)&dh[off] = pack_h2(rx, ry);
                    }
                }
            }
        }
    }
}

// ---------------- flash attention, single-pass fp16, 2 CTAs/SM ----------------
#define FL_Q 0u
#define FL_STG 16384u
#define FL_SSZ 16384u              // Khi 8KB + Vhi 8KB
#define FL_SMEM (FL_STG + 2 * FL_SSZ)   // 49152

__global__ __launch_bounds__(256, 2)
void flash_mma(const __half* __restrict__ qh_g,
               const __half* __restrict__ kh_g, const __half* __restrict__ vh_g,
               __half* __restrict__ oh_g)
{
    extern __shared__ char smem[];
    const uint32_t sb = smem_u32(smem);
    const int tid = threadIdx.x, wid = tid >> 5, lane = tid & 31;
    const int bh = blockIdx.y;
    const int qb = gridDim.x - 1 - blockIdx.x;     // heavy tiles first
    const int qbase = qb * 128;
    const size_t base = (size_t)bh * TSEQ * HD;
    const int nkb = 2 * qb + 2;

    auto ldq = [&]() {
        #pragma unroll
        for (int t = 0; t < 4; t++) {
            int idx = tid + t * 256;
            int row = idx >> 3, ch = idx & 7;
            uint32_t so = (uint32_t)(row * 128 + ((ch ^ (row & 7)) * 16));
            cpasync16(sb + FL_Q + so, qh_g + base + (size_t)(qbase + row) * HD + ch * 8);
        }
    };
    auto ldkv = [&](int kb, int stg) {
        const uint32_t st = sb + FL_STG + (uint32_t)stg * FL_SSZ;
        #pragma unroll
        for (int t = 0; t < 2; t++) {
            int idx = tid + t * 256;
            int row = idx >> 3, ch = idx & 7;
            uint32_t so = (uint32_t)(row * 128 + ((ch ^ (row & 7)) * 16));
            size_t g = base + (size_t)(kb * 64 + row) * HD + ch * 8;
            cpasync16(st + so,        kh_g + g);
            cpasync16(st + 8192 + so, vh_g + g);
        }
        CP_COMMIT();
    };

    ldq();
    ldkv(0, 0);

    const int arow = wid * 16 + (lane & 15);
    const int akoff = lane >> 4;
    const int brow_off = (lane & 7) + ((lane >> 4) << 3);
    const int bkoff = (lane >> 3) & 1;
    const int vrow_off = (lane & 7) + (((lane >> 3) & 1) << 3);
    const int vcg = lane >> 4;

    uint32_t qh[4][4];
    float acc_o[8][4];
    #pragma unroll
    for (int nt = 0; nt < 8; nt++)
        #pragma unroll
        for (int q = 0; q < 4; q++) acc_o[nt][q] = 0.f;
    float m0 = -1e30f, m1 = -1e30f, l0 = 0.f, l1 = 0.f;

    const int r0g = qbase + wid * 16 + (lane >> 2);
    const int r1g = r0g + 8;

    for (int kb = 0; kb < nkb; kb++) {
        const int cur = kb & 1;
        if (kb + 1 < nkb) {
            ldkv(kb + 1, cur ^ 1);
            CP_WAIT1();
        } else {
            CP_WAIT0();
        }
        __syncthreads();

        if (kb == 0) {
            #pragma unroll
            for (int s4 = 0; s4 < 4; s4++) {
                uint32_t off = (uint32_t)(arow * 128 + (((2*s4 + akoff) ^ (arow & 7)) * 16));
                ldsm4(qh[s4], sb + FL_Q + off);
            }
        }

        const uint32_t st = sb + FL_STG + (uint32_t)cur * FL_SSZ;

        float s[8][4];
        #pragma unroll
        for (int nt = 0; nt < 8; nt++)
            #pragma unroll
            for (int q = 0; q < 4; q++) s[nt][q] = 0.f;

        #pragma unroll
        for (int s4 = 0; s4 < 4; s4++) {
            uint32_t kh[4][4];
            #pragma unroll
            for (int nt2 = 0; nt2 < 4; nt2++) {
                int row = nt2 * 16 + brow_off;
                uint32_t off = (uint32_t)(row * 128 + (((2*s4 + bkoff) ^ (row & 7)) * 16));
                ldsm4(kh[nt2], st + off);
            }
            #pragma unroll
            for (int nt = 0; nt < 8; nt++)
                mma_f16(s[nt], qh[s4], &kh[nt >> 1][(nt & 1) * 2]);
        }

        const int kbase = kb * 64;
        if (kb >= nkb - 2) {
            #pragma unroll
            for (int nt = 0; nt < 8; nt++) {
                int kg0 = kbase + nt * 8 + 2 * (lane & 3);
                if (kg0 > r0g)     s[nt][0] = -1e30f;
                if (kg0 + 1 > r0g) s[nt][1] = -1e30f;
                if (kg0 > r1g)     s[nt][2] = -1e30f;
                if (kg0 + 1 > r1g) s[nt][3] = -1e30f;
            }
        }

        float mx0 = -1e30f, mx1 = -1e30f;
        #pragma unroll
        for (int nt = 0; nt < 8; nt++) {
            mx0 = fmaxf(mx0, fmaxf(s[nt][0], s[nt][1]));
            mx1 = fmaxf(mx1, fmaxf(s[nt][2], s[nt][3]));
        }
        mx0 = fmaxf(mx0, __shfl_xor_sync(0xffffffffu, mx0, 1));
        mx0 = fmaxf(mx0, __shfl_xor_sync(0xffffffffu, mx0, 2));
        mx1 = fmaxf(mx1, __shfl_xor_sync(0xffffffffu, mx1, 1));
        mx1 = fmaxf(mx1, __shfl_xor_sync(0xffffffffu, mx1, 2));
        float mn0 = fmaxf(m0, mx0), mn1 = fmaxf(m1, mx1);
        float a0 = __expf(m0 - mn0), a1 = __expf(m1 - mn1);
        float sum0 = 0.f, sum1 = 0.f;
        #pragma unroll
        for (int nt = 0; nt < 8; nt++) {
            s[nt][0] = __expf(s[nt][0] - mn0);
            s[nt][1] = __expf(s[nt][1] - mn0);
            s[nt][2] = __expf(s[nt][2] - mn1);
            s[nt][3] = __expf(s[nt][3] - mn1);
            sum0 += s[nt][0] + s[nt][1];
            sum1 += s[nt][2] + s[nt][3];
        }
        sum0 += __shfl_xor_sync(0xffffffffu, sum0, 1);
        sum0 += __shfl_xor_sync(0xffffffffu, sum0, 2);
        sum1 += __shfl_xor_sync(0xffffffffu, sum1, 1);
        sum1 += __shfl_xor_sync(0xffffffffu, sum1, 2);
        l0 = l0 * a0 + sum0; m0 = mn0;
        l1 = l1 * a1 + sum1; m1 = mn1;
        #pragma unroll
        for (int nt = 0; nt < 8; nt++) {
            acc_o[nt][0] *= a0; acc_o[nt][1] *= a0;
            acc_o[nt][2] *= a1; acc_o[nt][3] *= a1;
        }

        uint32_t phi[4][4];
        #pragma unroll
        for (int j2 = 0; j2 < 4; j2++) {
            phi[j2][0] = pack_h2(s[2*j2][0],   s[2*j2][1]);
            phi[j2][1] = pack_h2(s[2*j2][2],   s[2*j2][3]);
            phi[j2][2] = pack_h2(s[2*j2+1][0], s[2*j2+1][1]);
            phi[j2][3] = pack_h2(s[2*j2+1][2], s[2*j2+1][3]);
        }

        #pragma unroll
        for (int j2 = 0; j2 < 4; j2++) {
            int vrow = j2 * 16 + vrow_off;
            #pragma unroll
            for (int g = 0; g < 4; g++) {
                int cg = g * 2 + vcg;
                uint32_t off = (uint32_t)(vrow * 128 + ((cg ^ (vrow & 7)) * 16));
                uint32_t vh[4];
                ldsm4t(vh, st + 8192 + off);
                mma_f16(acc_o[2*g],     phi[j2], &vh[0]);
                mma_f16(acc_o[2*g + 1], phi[j2], &vh[2]);
            }
        }
        __syncthreads();
    }

    const int b = bh >> 4, h = bh & 15;
    const float inv0 = 1.f / l0, inv1 = 1.f / l1;
    #pragma unroll
    for (int nt = 0; nt < 8; nt++) {
        int d = nt * 8 + 2 * (lane & 3);
        size_t o0 = ((size_t)(b * TSEQ + r0g)) * DM + h * HD + d;
        size_t o1 = ((size_t)(b * TSEQ + r1g)) * DM + h * HD + d;
        *(uint32_t*)&oh_g[o0] = pack_h2(acc_o[nt][0] * inv0, acc_o[nt][1] * inv0);
        *(uint32_t*)&oh_g[o1] = pack_h2(acc_o[nt][2] * inv1, acc_o[nt][3] * inv1);
    }
}

// ---------------------------------------------------------------------------
extern "C" void kernel_launch(void* const* d_in, const int* in_sizes, int n_in,
                              void* d_out, int out_size)
{
    (void)in_sizes; (void)n_in; (void)out_size;
    const float* x     = (const float*)d_in[0];
    const float* qkv_w = (const float*)d_in[1];
    const float* qkv_b = (const float*)d_in[2];
    const float* out_w = (const float*)d_in[3];
    const float* out_b = (const float*)d_in[4];
    float* out = (float*)d_out;

    __half *xh, *w1h, *w2h, *ah, *qh, *kh, *vh;
    cudaGetSymbolAddress((void**)&xh,  g_xh);
    cudaGetSymbolAddress((void**)&w1h, g_w1h);
    cudaGetSymbolAddress((void**)&w2h, g_w2h);
    cudaGetSymbolAddress((void**)&ah,  g_ah);
    cudaGetSymbolAddress((void**)&qh,  g_qh);
    cudaGetSymbolAddress((void**)&kh,  g_kh);
    cudaGetSymbolAddress((void**)&vh,  g_vh);

    cudaFuncSetAttribute(mma_gemm<true>,  cudaFuncAttributeMaxDynamicSharedMemorySize, GEMM_SMEM);
    cudaFuncSetAttribute(mma_gemm<false>, cudaFuncAttributeMaxDynamicSharedMemorySize, GEMM_SMEM);
    cudaFuncSetAttribute(flash_mma, cudaFuncAttributeMaxDynamicSharedMemorySize, FL_SMEM);

    // 0) fp16 converts
    cvt3_kernel<<<(SPLIT_TOT + 255)/256, 256>>>(x, qkv_w, out_w);

    // 1) QKV projection (persistent) -> fp16 q,k,v in [B,H,T,Hd], q pre-scaled
    {
        int ntile = (MTOT/128) * (3*DM/128);
        int grid = ntile < 296 ? ntile : 296;
        mma_gemm<true><<<grid, 256, GEMM_SMEM>>>(xh, w1h, qkv_b, nullptr, 3*DM);
    }

    // 2) flash attention -> g_ah [B,T,D] (fp16)
    dim3 g2(TSEQ/128, BDIM*NH);
    flash_mma<<<g2, 256, FL_SMEM>>>(qh, kh, vh, ah);

    // 3) output projection (persistent) -> d_out
    {
        int ntile = (MTOT/128) * (DM/128);
        int grid = ntile < 296 ? ntile : 296;
        mma_gemm<false><<<grid, 256, GEMM_SMEM>>>(ah, w2h, out_b, out, DM);
    }
}